// round 7
// baseline (speedup 1.0000x reference)
#include <cuda_runtime.h>
#include <cuda_bf16.h>
#include <math.h>

#define B_  32
#define T_  256
#define D_  1024
#define D3_ 3072
#define TB_ 8192
#define L_  2
#define NCTA_ 128

// ---------------- device scratch (globals: allocation-free) ----------------
__device__ __nv_bfloat16 g_Wih_bf[2*L_*D3_*D_];   // [dir][layer][3072][1024]
__device__ __nv_bfloat16 g_x_bf [TB_*D_];         // layer-0 input  [T*B][D]
__device__ __nv_bfloat16 g_yf_bf[TB_*D_];         // fwd stack layer output
__device__ __nv_bfloat16 g_yb_bf[TB_*D_];         // bwd stack layer output
__device__ float         g_xg[2][TB_*D3_];        // per-dir input gates
__device__ __nv_bfloat16 g_hbf[2][2*B_*D_];       // bf16 h, ping-pong by phase
__device__ float         g_outvals[TB_];

// per-CTA step flags (one 128B line each) + init barrier state
__device__ unsigned g_flag[2][64][32];
__device__ unsigned g_barc2[2*32];
__device__ unsigned g_barg2[2*32];

// mma.sync m16n8k16 row.col f32.bf16.bf16.f32
#define MMA_BF16(d, a0,a1,a2,a3, b0,b1) \
  asm volatile("mma.sync.aligned.m16n8k16.row.col.f32.bf16.bf16.f32 " \
    "{%0,%1,%2,%3},{%4,%5,%6,%7},{%8,%9},{%0,%1,%2,%3};\n" \
    : "+f"(d[0]), "+f"(d[1]), "+f"(d[2]), "+f"(d[3]) \
    : "r"(a0), "r"(a1), "r"(a2), "r"(a3), "r"(b0), "r"(b1))

__device__ __forceinline__ void ldsm4(unsigned* r, unsigned a) {
  asm volatile("ldmatrix.sync.aligned.m8n8.x4.shared.b16 {%0,%1,%2,%3}, [%4];"
    : "=r"(r[0]), "=r"(r[1]), "=r"(r[2]), "=r"(r[3]) : "r"(a));
}

// L2-coherent (L1-bypassing) vector load — cross-CTA h ping-pong
__device__ __forceinline__ uint4 ldcg4(const __nv_bfloat16* p) {
  uint4 v;
  asm volatile("ld.global.cg.v4.b32 {%0,%1,%2,%3}, [%4];"
    : "=r"(v.x), "=r"(v.y), "=r"(v.z), "=r"(v.w) : "l"(p));
  return v;
}

__device__ __forceinline__ unsigned ld_acq(const unsigned* p) {
  unsigned v;
  asm volatile("ld.acquire.gpu.global.u32 %0, [%1];" : "=r"(v) : "l"(p));
  return v;
}
__device__ __forceinline__ void st_rel(unsigned* p, unsigned v) {
  asm volatile("st.release.gpu.global.u32 [%0], %1;" :: "l"(p), "r"(v));
}

// fast tanh via exp2-based __expf: (1-e)/(1+e), e=exp(-2x); clamp for safety
__device__ __forceinline__ float fast_tanh(float x) {
  float xc = fminf(fmaxf(x, -30.f), 30.f);
  float e = __expf(-2.f*xc);
  return (1.f - e) * __frcp_rn(1.f + e);
}

// sense-reversing per-stack grid barrier (init only)
__device__ __forceinline__ void gridbar2(int s, unsigned nc) {
  __syncthreads();
  if (threadIdx.x == 0) {
    __threadfence();
    volatile unsigned* genp = (volatile unsigned*)&g_barg2[s*32];
    unsigned gen = *genp;
    if (atomicAdd(&g_barc2[s*32], 1u) == nc - 1u) {
      g_barc2[s*32] = 0;
      __threadfence();
      *genp = gen + 1;
    } else {
      while (*genp == gen) { }
      __threadfence();
    }
  }
  __syncthreads();
}

// ---------------- weight conversion fp32 -> bf16 (Wih only) ----------------
__global__ void k_convw(const float* __restrict__ Wih_f, const float* __restrict__ Wih_b) {
  const int N = L_*D3_*D_;
  for (int i = blockIdx.x*blockDim.x + threadIdx.x; i < N; i += gridDim.x*blockDim.x) {
    g_Wih_bf[i]     = __float2bfloat16(Wih_f[i]);
    g_Wih_bf[N + i] = __float2bfloat16(Wih_b[i]);
  }
}

// ---------------- input projections + concat -> x[T*B][D] bf16 ----------------
__global__ __launch_bounds__(256) void k_proj(const float* __restrict__ input, const float* __restrict__ cond,
    const float* __restrict__ Wc, const float* __restrict__ bc,
    const float* __restrict__ Wi, const float* __restrict__ bi) {
  int t = blockIdx.x;
  int tid = threadIdx.x;
  __shared__ float cond_s[B_][80];
  __shared__ float in_s[B_][72];
  __shared__ float wbuf[64][80];
  __shared__ float bias_s[64];
  for (int i = tid; i < B_*80; i += 256) {
    int b = i / 80, j = i % 80;
    cond_s[b][j] = cond[((size_t)b*T_ + t)*80 + j];
  }
  for (int i = tid; i < B_*72; i += 256) {
    int b = i / 72, j = i % 72;
    in_s[b][j] = input[((size_t)b*T_ + t)*72 + j];
  }
  __syncthreads();
  for (int chunk = 0; chunk < 16; chunk++) {
    int dbase = chunk*64;
    int width = (dbase < 512) ? 80 : 72;
    const float* Wsrc = (dbase < 512) ? (Wc + (size_t)dbase*80) : (Wi + (size_t)(dbase-512)*72);
    for (int i = tid; i < 64*width; i += 256) wbuf[i/width][i%width] = Wsrc[i];
    if (tid < 64) bias_s[tid] = (dbase < 512) ? bc[dbase+tid] : bi[dbase-512+tid];
    __syncthreads();
    for (int i = tid; i < B_*64; i += 256) {
      int b = i & 31, dd = i >> 5;
      const float* act = (dbase < 512) ? &cond_s[b][0] : &in_s[b][0];
      float a = bias_s[dd];
      const float* w = &wbuf[dd][0];
      #pragma unroll 8
      for (int j = 0; j < width; j++) a += w[j]*act[j];
      a = fmaxf(a, 0.f);
      g_x_bf[((size_t)t*B_ + b)*D_ + dbase + dd] = __float2bfloat16(a);
    }
    __syncthreads();
  }
}

// ---------------- xg = A @ Wih^T + bih   (M=8192, N=3072, K=1024, bf16 mma) ----------------
__global__ __launch_bounds__(256) void k_gemm(int layer,
    const float* __restrict__ bih_f, const float* __restrict__ bih_b) {
  int dir = blockIdx.z;
  const __nv_bfloat16* A = (layer == 0) ? g_x_bf : (dir ? g_yb_bf : g_yf_bf);
  const __nv_bfloat16* W = g_Wih_bf + (size_t)(dir*L_ + layer)*D3_*D_;
  const float* bias = (dir ? bih_b : bih_f) + (size_t)layer*D3_;
  float* C = g_xg[dir];
  int m0 = blockIdx.y*128, n0 = blockIdx.x*64;

  __shared__ alignas(16) __nv_bfloat16 As[2][128][40];
  __shared__ alignas(16) __nv_bfloat16 Bs[2][64][40];

  int tid = threadIdx.x, lane = tid&31, warp = tid>>5;
  int wm = warp>>1, wn = warp&1, tg = lane>>2, tc = lane&3;
  int lr = tid>>2, lc = (tid&3)*8;

  float acc[2][4][4];
  #pragma unroll
  for (int i=0;i<2;i++)
    #pragma unroll
    for(int j=0;j<4;j++)
      #pragma unroll
      for(int k=0;k<4;k++) acc[i][j][k]=0.f;

  uint4 va0, va1, vb0;
  va0 = *(const uint4*)&A[(size_t)(m0+lr)*D_ + lc];
  va1 = *(const uint4*)&A[(size_t)(m0+lr+64)*D_ + lc];
  vb0 = *(const uint4*)&W[(size_t)(n0+lr)*D_ + lc];
  *(uint4*)&As[0][lr][lc]    = va0;
  *(uint4*)&As[0][lr+64][lc] = va1;
  *(uint4*)&Bs[0][lr][lc]    = vb0;
  __syncthreads();

  int cur = 0;
  for (int it = 0; it < 32; it++) {
    if (it < 31) {
      int kc = (it+1)*32;
      va0 = *(const uint4*)&A[(size_t)(m0+lr)*D_ + kc + lc];
      va1 = *(const uint4*)&A[(size_t)(m0+lr+64)*D_ + kc + lc];
      vb0 = *(const uint4*)&W[(size_t)(n0+lr)*D_ + kc + lc];
    }
    #pragma unroll
    for (int s = 0; s < 32; s += 16) {
      unsigned a[2][4];
      #pragma unroll
      for (int mt = 0; mt < 2; mt++) {
        int r = wm*32 + mt*16 + tg;
        a[mt][0] = *(const unsigned*)&As[cur][r  ][s + 2*tc];
        a[mt][1] = *(const unsigned*)&As[cur][r+8][s + 2*tc];
        a[mt][2] = *(const unsigned*)&As[cur][r  ][s + 2*tc + 8];
        a[mt][3] = *(const unsigned*)&As[cur][r+8][s + 2*tc + 8];
      }
      #pragma unroll
      for (int nt = 0; nt < 4; nt++) {
        int nr = wn*32 + nt*8 + tg;
        unsigned b0 = *(const unsigned*)&Bs[cur][nr][s + 2*tc];
        unsigned b1 = *(const unsigned*)&Bs[cur][nr][s + 2*tc + 8];
        MMA_BF16(acc[0][nt], a[0][0],a[0][1],a[0][2],a[0][3], b0, b1);
        MMA_BF16(acc[1][nt], a[1][0],a[1][1],a[1][2],a[1][3], b0, b1);
      }
    }
    if (it < 31) {
      int nxt = cur^1;
      *(uint4*)&As[nxt][lr][lc]    = va0;
      *(uint4*)&As[nxt][lr+64][lc] = va1;
      *(uint4*)&Bs[nxt][lr][lc]    = vb0;
    }
    __syncthreads();
    cur ^= 1;
  }

  #pragma unroll
  for (int mt=0; mt<2; mt++) {
    #pragma unroll
    for (int nt=0; nt<4; nt++) {
      int gr = m0 + wm*32 + mt*16 + tg;
      int gc = n0 + wn*32 + nt*8 + 2*tc;
      C[(size_t)gr*D3_ + gc]       = acc[mt][nt][0] + bias[gc];
      C[(size_t)gr*D3_ + gc + 1]   = acc[mt][nt][1] + bias[gc+1];
      C[(size_t)(gr+8)*D3_ + gc]   = acc[mt][nt][2] + bias[gc];
      C[(size_t)(gr+8)*D3_ + gc+1] = acc[mt][nt][3] + bias[gc+1];
    }
  }
}

// ---------------- persistent GRU recurrence: flag dataflow, no CTA-wide syncs ----------------
// grid 128 (single wave): stack = bid>>6, 16-column block = bid&63. block 384 threads.
// Warp grid: wk = warp&3 (K-group of 256 h-cols), wn = warp>>2 (n-group of 16 gate cols).
// Poll: only wn==0 warps. Named bars: 1+wk (96 thr, K-group), 5 (256 thr, gate warps),
// 6 (384: warps 0-7 sync, warps 8-11 arrive). xg_s/hgp double-buffered by t&1.
#define HS_STRIDE 1032
#define OFF_WS   66048
#define OFF_XG   (OFF_WS + 99072)           // 2 x [32][48] f32   = 12288
#define OFF_HGP  (OFF_XG + 12288)           // 2 x [4][32][49] f32 = 50176
#define OFF_BHH  (OFF_HGP + 50176)
#define RNN_SMEM (OFF_BHH + 192)            // 227776 bytes

__global__ __launch_bounds__(384, 1) void k_rnn(int layer,
    const float* __restrict__ Whh_f, const float* __restrict__ Whh_b,
    const float* __restrict__ bhh_f, const float* __restrict__ bhh_b) {
  extern __shared__ char smem_raw[];
  __nv_bfloat16* hs  = (__nv_bfloat16*)smem_raw;                 // [32][1032]
  __nv_bfloat16* Ws  = (__nv_bfloat16*)(smem_raw + OFF_WS);      // [48][1032]
  float*         xg_s= (float*)(smem_raw + OFF_XG);              // [2][32][48]
  float*         hgp = (float*)(smem_raw + OFF_HGP);             // [2][4][32][49]
  float*         bhh_s=(float*)(smem_raw + OFF_BHH);             // [48]

  int stack = blockIdx.x >> 6;
  int blk   = blockIdx.x & 63;
  int cgb   = blk * 16;
  const float* Whh = (stack ? Whh_b : Whh_f) + (size_t)layer*D3_*D_;
  const float* xg = g_xg[stack];
  const float* bhh = (stack ? bhh_b : bhh_f) + (size_t)layer*D3_;
  __nv_bfloat16* ys = stack ? g_yb_bf : g_yf_bf;

  int tid = threadIdx.x, lane = tid&31, warp = tid>>5;
  int wk = warp & 3, wn = warp >> 2;
  int tg = lane>>2, tc = lane&3;
  int gtid = wn*32 + lane;              // index within 3-warp K-group (0..95)

  // ---- preload Whh tile (fp32 -> bf16) into SMEM, once per layer ----
  for (int i = tid; i < 12288; i += 384) {
    int row = i >> 8, q4 = (i & 255) * 4;
    size_t grow = (size_t)((row >> 4)*D_ + cgb + (row & 15));
    float4 v = *(const float4*)&Whh[grow*D_ + q4];
    __nv_bfloat16 b4[4] = { __float2bfloat16(v.x), __float2bfloat16(v.y),
                            __float2bfloat16(v.z), __float2bfloat16(v.w) };
    *(uint2*)&Ws[row*HS_STRIDE + q4] = *(uint2*)b4;
  }
  for (int i = tid; i < 48; i += 384)
    bhh_s[i] = bhh[(i>>4)*D_ + cgb + (i&15)];

  // ---- init: reset flag, zero h (fp32 in regs, bf16 phase-0 buffer) ----
  if (tid == 0) g_flag[stack][blk][0] = 0;
  float hp0 = 0.f, hp1 = 0.f;
  for (int i = tid; i < 512; i += 384) {
    int b = i & 31, j = i >> 5;
    g_hbf[0][(size_t)stack*B_*D_ + (size_t)b*D_ + cgb + j] = __float2bfloat16(0.f);
  }
  gridbar2(stack, 64);

  // gate mapping (coalesced): thread tid<256 owns (gb, gj) and (gb+16, gj)
  int gj = tid & 15, gb = tid >> 4;

  // xg prefetch mapping: one uint4 per thread
  int pb = tid / 12, prem = tid % 12, pg = prem >> 2, pq = prem & 3;
  const float* xg_src = &xg[(size_t)pb*D3_ + (size_t)pg*D_ + cgb + pq*4];

  // ldmatrix base addresses (smem 32-bit)
  unsigned hs_sm = (unsigned)__cvta_generic_to_shared(hs);
  unsigned ws_sm = (unsigned)__cvta_generic_to_shared(Ws);
  unsigned aBase0 = hs_sm + 2u*((lane&15)*HS_STRIDE + ((lane>>4)*8) + wk*256);
  unsigned aBase1 = aBase0 + 2u*16*HS_STRIDE;
  unsigned bBase  = ws_sm + 2u*((wn*16 + (lane&7) + ((lane>>4)*8))*HS_STRIDE
                              + (((lane>>3)&1)*8) + wk*256);

  // poll target: K-group wk <- producer CTAs 16wk..16wk+15 (only wn==0 warps use)
  const unsigned* flagp = &g_flag[stack][wk*16 + (lane & 15)][0];
  unsigned* myflag = &g_flag[stack][blk][0];

  uint4 vxg = *(const uint4*)xg_src;   // xg[t=0]

  for (int t = 0; t < T_; t++) {
    int buf = t & 1;
    const __nv_bfloat16* hin = g_hbf[buf]     + (size_t)stack*B_*D_;
    __nv_bfloat16*       hout= g_hbf[buf ^ 1] + (size_t)stack*B_*D_;
    float* xgb = xg_s + buf*1536;
    float* hgb = hgp  + buf*6272;

    // commit prefetched xg[t] (double-buffered: no race with gate reads of t-1)
    *(uint4*)&xgb[pb*48 + pg*16 + pq*4] = vxg;
    if (t + 1 < T_) vxg = *(const uint4*)(xg_src + (size_t)(t+1)*B_*D3_);

    // ---- single poll warp per K-group waits for its 16 producers ----
    if (wn == 0) {
      unsigned want = (unsigned)t;
      unsigned v = ld_acq(flagp);
      while (!__all_sync(0xffffffffu, v >= want)) v = ld_acq(flagp);
    }
    asm volatile("bar.sync %0, %1;" :: "r"(wk + 1), "r"(96) : "memory");

    // ---- group loads its h chunk: cols [256wk, 256wk+256) x 32 batches ----
    #pragma unroll 4
    for (int i = gtid; i < 1024; i += 96) {
      int b = i >> 5, c8 = (i & 31) * 8;
      uint4 v = ldcg4(&hin[(size_t)b*D_ + wk*256 + c8]);
      *(uint4*)&hs[b*HS_STRIDE + wk*256 + c8] = v;
    }
    asm volatile("bar.sync %0, %1;" :: "r"(wk + 1), "r"(96) : "memory");

    // ---- MMA: warp (wk, wn): m32 x n16 over K-chunk 256 ----
    float acc[2][2][4];
    #pragma unroll
    for (int i=0;i<2;i++)
      #pragma unroll
      for (int j=0;j<2;j++)
        #pragma unroll
        for (int q=0;q<4;q++) acc[i][j][q]=0.f;
    {
      unsigned a0A = aBase0, a1A = aBase1, bA = bBase;
      #pragma unroll 4
      for (int kt = 0; kt < 16; kt++) {
        unsigned fa0[4], fa1[4], fb[4];
        ldsm4(fa0, a0A);
        ldsm4(fa1, a1A);
        ldsm4(fb, bA);
        MMA_BF16(acc[0][0], fa0[0],fa0[1],fa0[2],fa0[3], fb[0], fb[1]);
        MMA_BF16(acc[0][1], fa0[0],fa0[1],fa0[2],fa0[3], fb[2], fb[3]);
        MMA_BF16(acc[1][0], fa1[0],fa1[1],fa1[2],fa1[3], fb[0], fb[1]);
        MMA_BF16(acc[1][1], fa1[0],fa1[1],fa1[2],fa1[3], fb[2], fb[3]);
        a0A += 32; a1A += 32; bA += 32;
      }
    }
    // stage K-split partials (double-buffered)
    #pragma unroll
    for (int mf = 0; mf < 2; mf++) {
      #pragma unroll
      for (int nf = 0; nf < 2; nf++) {
        int r = mf*16 + tg;
        int col = wn*16 + nf*8 + 2*tc;
        float* p = &hgb[(wk*32 + r)*49 + col];
        p[0]      = acc[mf][nf][0];
        p[1]      = acc[mf][nf][1];
        p[49*8]   = acc[mf][nf][2];
        p[49*8+1] = acc[mf][nf][3];
      }
    }

    if (warp < 8) {
      // wait for all 12 warps' partials
      asm volatile("bar.sync 6, 384;" ::: "memory");

      // ---- gate fusion: 256 threads x 2 elements, h in registers ----
      float hb0f, hb1f;
      {
        int b = gb, j = gj;
        float xr = xgb[b*48 + j];
        float xz = xgb[b*48 + 16 + j];
        float xn = xgb[b*48 + 32 + j];
        float hr = bhh_s[j], hz = bhh_s[16+j], hn = bhh_s[32+j];
        #pragma unroll
        for (int k = 0; k < 4; k++) {
          const float* p = &hgb[(k*32 + b)*49];
          hr += p[j]; hz += p[16+j]; hn += p[32+j];
        }
        float r  = 1.f/(1.f + __expf(-(xr+hr)));
        float z  = 1.f/(1.f + __expf(-(xz+hz)));
        float nn = fast_tanh(xn + r*hn);
        hp0 = (1.f - z)*nn + z*hp0;
        hb0f = hp0;
        hout[(size_t)b*D_ + cgb + j] = __float2bfloat16(hp0);
      }
      {
        int b = gb + 16, j = gj;
        float xr = xgb[b*48 + j];
        float xz = xgb[b*48 + 16 + j];
        float xn = xgb[b*48 + 32 + j];
        float hr = bhh_s[j], hz = bhh_s[16+j], hn = bhh_s[32+j];
        #pragma unroll
        for (int k = 0; k < 4; k++) {
          const float* p = &hgb[(k*32 + b)*49];
          hr += p[j]; hz += p[16+j]; hn += p[32+j];
        }
        float r  = 1.f/(1.f + __expf(-(xr+hr)));
        float z  = 1.f/(1.f + __expf(-(xz+hz)));
        float nn = fast_tanh(xn + r*hn);
        hp1 = (1.f - z)*nn + z*hp1;
        hb1f = hp1;
        hout[(size_t)b*D_ + cgb + j] = __float2bfloat16(hp1);
      }
      // hout visible -> publish flag, then off-chain ys stores
      asm volatile("bar.sync 5, 256;" ::: "memory");
      if (tid == 0) st_rel(myflag, (unsigned)(t + 1));
      ys[((size_t)t*B_ + gb)*D_ + cgb + gj]        = __float2bfloat16(hb0f);
      ys[((size_t)t*B_ + gb + 16)*D_ + cgb + gj]   = __float2bfloat16(hb1f);
    } else {
      asm volatile("bar.arrive 6, 384;" ::: "memory");
    }
  }
}

// ---------------- output head ----------------
__global__ __launch_bounds__(128) void k_out1(const float* __restrict__ Wo, const float* __restrict__ bo) {
  int row = blockIdx.x;
  int tid = threadIdx.x;
  float acc = 0.f;
  for (int d = tid; d < D_; d += 128)
    acc += (__bfloat162float(g_yf_bf[(size_t)row*D_+d]) +
            __bfloat162float(g_yb_bf[(size_t)row*D_+d])) * Wo[d];
  #pragma unroll
  for (int o = 16; o; o >>= 1) acc += __shfl_xor_sync(0xffffffffu, acc, o);
  __shared__ float ws[4];
  if ((tid & 31) == 0) ws[tid>>5] = acc;
  __syncthreads();
  if (tid == 0) {
    float s = ws[0]+ws[1]+ws[2]+ws[3] + bo[0];
    g_outvals[row] = 1.f/(1.f + expf(-s));
  }
}

__global__ void k_out2(float* out) {
  __shared__ float sm[256];
  int tid = threadIdx.x;
  float s = 0.f;
  for (int i = tid; i < TB_; i += 256) s += g_outvals[i];
  sm[tid] = s;
  __syncthreads();
  for (int o = 128; o; o >>= 1) { if (tid < o) sm[tid] += sm[tid+o]; __syncthreads(); }
  if (tid == 0) out[0] = sm[0] / (float)TB_;
}

// ---------------- launch ----------------
extern "C" void kernel_launch(void* const* d_in, const int* in_sizes, int n_in,
                              void* d_out, int out_size) {
  (void)in_sizes; (void)n_in; (void)out_size;
  const float* input = (const float*)d_in[0];
  const float* cond  = (const float*)d_in[1];
  const float* Wc    = (const float*)d_in[2];
  const float* bc    = (const float*)d_in[3];
  const float* Wi    = (const float*)d_in[4];
  const float* bi    = (const float*)d_in[5];
  const float* Wih_f = (const float*)d_in[6];
  const float* Whh_f = (const float*)d_in[7];
  const float* bih_f = (const float*)d_in[8];
  const float* bhh_f = (const float*)d_in[9];
  const float* Wih_b = (const float*)d_in[10];
  const float* Whh_b = (const float*)d_in[11];
  const float* bih_b = (const float*)d_in[12];
  const float* bhh_b = (const float*)d_in[13];
  const float* Wo    = (const float*)d_in[14];
  const float* bo    = (const float*)d_in[15];
  float* out = (float*)d_out;

  cudaFuncSetAttribute(k_rnn, cudaFuncAttributeMaxDynamicSharedMemorySize, RNN_SMEM);

  k_convw<<<4096, 256>>>(Wih_f, Wih_b);
  k_proj<<<256, 256>>>(input, cond, Wc, bc, Wi, bi);
  for (int l = 0; l < L_; l++) {
    k_gemm<<<dim3(48, 64, 2), 256>>>(l, bih_f, bih_b);
    k_rnn<<<NCTA_, 384, RNN_SMEM>>>(l, Whh_f, Whh_b, bhh_f, bhh_b);
  }
  k_out1<<<TB_, 128>>>(Wo, bo);
  k_out2<<<1, 256>>>(out);
}

// round 8
// speedup vs baseline: 1.0851x; 1.0851x over previous
#include <cuda_runtime.h>
#include <cuda_bf16.h>
#include <math.h>

#define B_  32
#define T_  256
#define D_  1024
#define D3_ 3072
#define TB_ 8192
#define L_  2
#define NCTA_ 128

__device__ __nv_bfloat16 g_Wih_bf[2*L_*D3_*D_];
__device__ __nv_bfloat16 g_x_bf [TB_*D_];
__device__ __nv_bfloat16 g_yf_bf[TB_*D_];
__device__ __nv_bfloat16 g_yb_bf[TB_*D_];
__device__ float         g_xg[2][TB_*D3_];
__device__ __nv_bfloat16 g_hbf[2][2*B_*D_];
__device__ float         g_outvals[TB_];

__device__ unsigned g_flag[2][64][32];
__device__ unsigned g_barc2[2*32];
__device__ unsigned g_barg2[2*32];

#define MMA_BF16(d, a0,a1,a2,a3, b0,b1) \
  asm volatile("mma.sync.aligned.m16n8k16.row.col.f32.bf16.bf16.f32 " \
    "{%0,%1,%2,%3},{%4,%5,%6,%7},{%8,%9},{%0,%1,%2,%3};\n" \
    : "+f"(d[0]), "+f"(d[1]), "+f"(d[2]), "+f"(d[3]) \
    : "r"(a0), "r"(a1), "r"(a2), "r"(a3), "r"(b0), "r"(b1))

__device__ __forceinline__ void ldsm4(unsigned* r, unsigned a) {
  asm volatile("ldmatrix.sync.aligned.m8n8.x4.shared.b16 {%0,%1,%2,%3}, [%4];"
    : "=r"(r[0]), "=r"(r[1]), "=r"(r[2]), "=r"(r[3]) : "r"(a));
}
__device__ __forceinline__ void cpasync16(unsigned dst, const void* src) {
  asm volatile("cp.async.cg.shared.global [%0], [%1], 16;" :: "r"(dst), "l"(src));
}
#define CP_COMMIT() asm volatile("cp.async.commit_group;" ::: "memory")
#define CP_WAIT(n)  asm volatile("cp.async.wait_group %0;" :: "n"(n) : "memory")
#define BAR_SYNC(id,cnt) asm volatile("bar.sync %0,%1;"::"r"(id),"r"(cnt):"memory")
#define BAR_ARR(id,cnt)  asm volatile("bar.arrive %0,%1;"::"r"(id),"r"(cnt):"memory")

__device__ __forceinline__ unsigned ld_acq(const unsigned* p) {
  unsigned v;
  asm volatile("ld.acquire.gpu.global.u32 %0, [%1];" : "=r"(v) : "l"(p));
  return v;
}
__device__ __forceinline__ void st_rel(unsigned* p, unsigned v) {
  asm volatile("st.release.gpu.global.u32 [%0], %1;" :: "l"(p), "r"(v));
}
__device__ __forceinline__ float fast_tanh(float x) {
  float xc = fminf(fmaxf(x, -30.f), 30.f);
  float e = __expf(-2.f*xc);
  return (1.f - e) * __frcp_rn(1.f + e);
}
__device__ __forceinline__ void gridbar2(int s, unsigned nc) {
  __syncthreads();
  if (threadIdx.x == 0) {
    __threadfence();
    volatile unsigned* genp = (volatile unsigned*)&g_barg2[s*32];
    unsigned gen = *genp;
    if (atomicAdd(&g_barc2[s*32], 1u) == nc - 1u) {
      g_barc2[s*32] = 0;
      __threadfence();
      *genp = gen + 1;
    } else {
      while (*genp == gen) { }
      __threadfence();
    }
  }
  __syncthreads();
}

__global__ void k_convw(const float* __restrict__ Wih_f, const float* __restrict__ Wih_b) {
  const int N = L_*D3_*D_;
  for (int i = blockIdx.x*blockDim.x + threadIdx.x; i < N; i += gridDim.x*blockDim.x) {
    g_Wih_bf[i]     = __float2bfloat16(Wih_f[i]);
    g_Wih_bf[N + i] = __float2bfloat16(Wih_b[i]);
  }
}

__global__ __launch_bounds__(256) void k_proj(const float* __restrict__ input, const float* __restrict__ cond,
    const float* __restrict__ Wc, const float* __restrict__ bc,
    const float* __restrict__ Wi, const float* __restrict__ bi) {
  int t = blockIdx.x;
  int tid = threadIdx.x;
  __shared__ float cond_s[B_][80];
  __shared__ float in_s[B_][72];
  __shared__ float wbuf[64][80];
  __shared__ float bias_s[64];
  for (int i = tid; i < B_*80; i += 256) {
    int b = i / 80, j = i % 80;
    cond_s[b][j] = cond[((size_t)b*T_ + t)*80 + j];
  }
  for (int i = tid; i < B_*72; i += 256) {
    int b = i / 72, j = i % 72;
    in_s[b][j] = input[((size_t)b*T_ + t)*72 + j];
  }
  __syncthreads();
  for (int chunk = 0; chunk < 16; chunk++) {
    int dbase = chunk*64;
    int width = (dbase < 512) ? 80 : 72;
    const float* Wsrc = (dbase < 512) ? (Wc + (size_t)dbase*80) : (Wi + (size_t)(dbase-512)*72);
    for (int i = tid; i < 64*width; i += 256) wbuf[i/width][i%width] = Wsrc[i];
    if (tid < 64) bias_s[tid] = (dbase < 512) ? bc[dbase+tid] : bi[dbase-512+tid];
    __syncthreads();
    for (int i = tid; i < B_*64; i += 256) {
      int b = i & 31, dd = i >> 5;
      const float* act = (dbase < 512) ? &cond_s[b][0] : &in_s[b][0];
      float a = bias_s[dd];
      const float* w = &wbuf[dd][0];
      #pragma unroll 8
      for (int j = 0; j < width; j++) a += w[j]*act[j];
      a = fmaxf(a, 0.f);
      g_x_bf[((size_t)t*B_ + b)*D_ + dbase + dd] = __float2bfloat16(a);
    }
    __syncthreads();
  }
}

__global__ __launch_bounds__(256) void k_gemm(int layer,
    const float* __restrict__ bih_f, const float* __restrict__ bih_b) {
  int dir = blockIdx.z;
  const __nv_bfloat16* A = (layer == 0) ? g_x_bf : (dir ? g_yb_bf : g_yf_bf);
  const __nv_bfloat16* W = g_Wih_bf + (size_t)(dir*L_ + layer)*D3_*D_;
  const float* bias = (dir ? bih_b : bih_f) + (size_t)layer*D3_;
  float* C = g_xg[dir];
  int m0 = blockIdx.y*128, n0 = blockIdx.x*64;

  __shared__ alignas(16) __nv_bfloat16 As[2][128][40];
  __shared__ alignas(16) __nv_bfloat16 Bs[2][64][40];

  int tid = threadIdx.x, lane = tid&31, warp = tid>>5;
  int wm = warp>>1, wn = warp&1, tg = lane>>2, tc = lane&3;
  int lr = tid>>2, lc = (tid&3)*8;

  float acc[2][4][4];
  #pragma unroll
  for (int i=0;i<2;i++)
    #pragma unroll
    for(int j=0;j<4;j++)
      #pragma unroll
      for(int k=0;k<4;k++) acc[i][j][k]=0.f;

  uint4 va0, va1, vb0;
  va0 = *(const uint4*)&A[(size_t)(m0+lr)*D_ + lc];
  va1 = *(const uint4*)&A[(size_t)(m0+lr+64)*D_ + lc];
  vb0 = *(const uint4*)&W[(size_t)(n0+lr)*D_ + lc];
  *(uint4*)&As[0][lr][lc]    = va0;
  *(uint4*)&As[0][lr+64][lc] = va1;
  *(uint4*)&Bs[0][lr][lc]    = vb0;
  __syncthreads();

  int cur = 0;
  for (int it = 0; it < 32; it++) {
    if (it < 31) {
      int kc = (it+1)*32;
      va0 = *(const uint4*)&A[(size_t)(m0+lr)*D_ + kc + lc];
      va1 = *(const uint4*)&A[(size_t)(m0+lr+64)*D_ + kc + lc];
      vb0 = *(const uint4*)&W[(size_t)(n0+lr)*D_ + kc + lc];
    }
    #pragma unroll
    for (int s = 0; s < 32; s += 16) {
      unsigned a[2][4];
      #pragma unroll
      for (int mt = 0; mt < 2; mt++) {
        int r = wm*32 + mt*16 + tg;
        a[mt][0] = *(const unsigned*)&As[cur][r  ][s + 2*tc];
        a[mt][1] = *(const unsigned*)&As[cur][r+8][s + 2*tc];
        a[mt][2] = *(const unsigned*)&As[cur][r  ][s + 2*tc + 8];
        a[mt][3] = *(const unsigned*)&As[cur][r+8][s + 2*tc + 8];
      }
      #pragma unroll
      for (int nt = 0; nt < 4; nt++) {
        int nr = wn*32 + nt*8 + tg;
        unsigned b0 = *(const unsigned*)&Bs[cur][nr][s + 2*tc];
        unsigned b1 = *(const unsigned*)&Bs[cur][nr][s + 2*tc + 8];
        MMA_BF16(acc[0][nt], a[0][0],a[0][1],a[0][2],a[0][3], b0, b1);
        MMA_BF16(acc[1][nt], a[1][0],a[1][1],a[1][2],a[1][3], b0, b1);
      }
    }
    if (it < 31) {
      int nxt = cur^1;
      *(uint4*)&As[nxt][lr][lc]    = va0;
      *(uint4*)&As[nxt][lr+64][lc] = va1;
      *(uint4*)&Bs[nxt][lr][lc]    = vb0;
    }
    __syncthreads();
    cur ^= 1;
  }

  #pragma unroll
  for (int mt=0; mt<2; mt++) {
    #pragma unroll
    for (int nt=0; nt<4; nt++) {
      int gr = m0 + wm*32 + mt*16 + tg;
      int gc = n0 + wn*32 + nt*8 + 2*tc;
      C[(size_t)gr*D3_ + gc]       = acc[mt][nt][0] + bias[gc];
      C[(size_t)gr*D3_ + gc + 1]   = acc[mt][nt][1] + bias[gc+1];
      C[(size_t)(gr+8)*D3_ + gc]   = acc[mt][nt][2] + bias[gc];
      C[(size_t)(gr+8)*D3_ + gc+1] = acc[mt][nt][3] + bias[gc+1];
    }
  }
}

// persistent recurrence: 512 thr = 12 MMA warps (wk=warp&3, wn=warp>>2) + 4 loader warps.
// ready bars 1+c (128), free bars 9+c (128), 13 partials (384), 14 gate (256).
#define HS_STRIDE 1032
#define OFF_WS   66048
#define OFF_XG   (OFF_WS + 99072)
#define OFF_HGP  (OFF_XG + 12288)
#define OFF_BHH  (OFF_HGP + 50176)
#define RNN_SMEM (OFF_BHH + 192)

__global__ __launch_bounds__(512, 1) void k_rnn(int layer,
    const float* __restrict__ Whh_f, const float* __restrict__ Whh_b,
    const float* __restrict__ bhh_f, const float* __restrict__ bhh_b) {
  extern __shared__ char smem_raw[];
  __nv_bfloat16* hs  = (__nv_bfloat16*)smem_raw;                 // [32][1032]
  __nv_bfloat16* Ws  = (__nv_bfloat16*)(smem_raw + OFF_WS);      // [48][1032]
  float*         xg_s= (float*)(smem_raw + OFF_XG);              // [2][32][48]
  float*         hgp = (float*)(smem_raw + OFF_HGP);             // [2][32][196]
  float*         bhh_s=(float*)(smem_raw + OFF_BHH);             // [48]

  int stack = blockIdx.x >> 6;
  int blk   = blockIdx.x & 63;
  int cgb   = blk * 16;
  const float* Whh = (stack ? Whh_b : Whh_f) + (size_t)layer*D3_*D_;
  const float* xg = g_xg[stack];
  const float* bhh = (stack ? bhh_b : bhh_f) + (size_t)layer*D3_;
  __nv_bfloat16* ys = stack ? g_yb_bf : g_yf_bf;

  int tid = threadIdx.x, lane = tid&31, warp = tid>>5;
  int wk = warp & 3, wn = warp >> 2;
  int tg = lane>>2, tc = lane&3;

  for (int i = tid; i < 12288; i += 512) {
    int row = i >> 8, q4 = (i & 255) * 4;
    size_t grow = (size_t)((row >> 4)*D_ + cgb + (row & 15));
    float4 v = *(const float4*)&Whh[grow*D_ + q4];
    __nv_bfloat16 b4[4] = { __float2bfloat16(v.x), __float2bfloat16(v.y),
                            __float2bfloat16(v.z), __float2bfloat16(v.w) };
    *(uint2*)&Ws[row*HS_STRIDE + q4] = *(uint2*)b4;
  }
  for (int i = tid; i < 48; i += 512)
    bhh_s[i] = bhh[(i>>4)*D_ + cgb + (i&15)];
  {
    uint4 z = make_uint4(0,0,0,0);
    for (int i = tid; i < 4096; i += 512) {
      int b = i >> 7, c8 = (i & 127) * 8;
      *(uint4*)&hs[b*HS_STRIDE + c8] = z;
    }
  }
  if (tid == 0) g_flag[stack][blk][0] = 0;
  gridbar2(stack, 64);

  unsigned hs_sm = (unsigned)__cvta_generic_to_shared(hs);
  unsigned ws_sm = (unsigned)__cvta_generic_to_shared(Ws);

  if (warp >= 12) {
    // ---------------- loader warp c ----------------
    int c = warp - 12;
    const size_t stk = (size_t)stack*B_*D_;
    for (int j = 0; j < T_ - 1; j++) {
      BAR_SYNC(9 + c, 128);                       // hs(t=j) consumed by group c
      const __nv_bfloat16* hin = g_hbf[(j + 1) & 1] + stk;
      unsigned want = (unsigned)(j + 1);
      #define POLLS(s) do { \
        const unsigned* fps = &g_flag[stack][c*16 + (s)*4 + (lane & 3)][0]; \
        unsigned v = ld_acq(fps); \
        while (!__all_sync(0xffffffffu, v >= want)) v = ld_acq(fps); \
      } while (0)
      #define ISSUES(s) do { \
        int base = c*256 + (s)*64; \
        _Pragma("unroll") \
        for (int it2 = 0; it2 < 8; it2++) { \
          int i2 = lane + it2*32; \
          int b2 = i2 >> 3, q2 = (i2 & 7)*8; \
          cpasync16(hs_sm + 2u*(unsigned)(b2*HS_STRIDE + base + q2), \
                    hin + (size_t)b2*D_ + base + q2); \
        } \
        CP_COMMIT(); \
      } while (0)
      POLLS(0); ISSUES(0);
      POLLS(1); ISSUES(1);
      CP_WAIT(1); BAR_ARR(1 + c, 128);
      POLLS(2); ISSUES(2);
      CP_WAIT(1); BAR_ARR(1 + c, 128);
      POLLS(3); ISSUES(3);
      CP_WAIT(1); BAR_ARR(1 + c, 128);
      CP_WAIT(0); BAR_ARR(1 + c, 128);
      #undef POLLS
      #undef ISSUES
    }
    BAR_SYNC(9 + c, 128);                         // balance t=T-1 free arrivals
  } else {
    // ---------------- MMA (+gate) warps ----------------
    int gj = tid & 15, gb = tid >> 4;
    int pb = tid / 12, prem = tid % 12, pg = prem >> 2, pq = prem & 3;
    const float* xg_src = &xg[(size_t)pb*D3_ + (size_t)pg*D_ + cgb + pq*4];
    unsigned* myflag = &g_flag[stack][blk][0];

    unsigned aBase0 = hs_sm + 2u*((lane&15)*HS_STRIDE + ((lane>>4)*8) + wk*256);
    unsigned aBase1 = aBase0 + 2u*16*HS_STRIDE;
    unsigned bBase  = ws_sm + 2u*((wn*16 + (lane&7) + ((lane>>4)*8))*HS_STRIDE
                                + (((lane>>3)&1)*8) + wk*256);
    float hp0 = 0.f, hp1 = 0.f;
    uint4 vxg = *(const uint4*)xg_src;

    for (int t = 0; t < T_; t++) {
      int buf = t & 1;
      float* xgb = xg_s + buf*1536;
      float* hgb = hgp  + buf*6272;

      *(uint4*)&xgb[pb*48 + pg*16 + pq*4] = vxg;
      if (t + 1 < T_) vxg = *(const uint4*)(xg_src + (size_t)(t+1)*B_*D3_);

      float acc[2][2][4];
      #pragma unroll
      for (int i=0;i<2;i++)
        #pragma unroll
        for (int j2=0;j2<2;j2++)
          #pragma unroll
          for (int q=0;q<4;q++) acc[i][j2][q]=0.f;

      #pragma unroll
      for (int s = 0; s < 4; s++) {
        if (t > 0) BAR_SYNC(1 + wk, 128);         // sub-chunk s of h(t) ready
        unsigned a0A = aBase0 + 128u*s, a1A = aBase1 + 128u*s, bA = bBase + 128u*s;
        #pragma unroll
        for (int kt = 0; kt < 4; kt++) {
          unsigned fa0[4], fa1[4], fb[4];
          ldsm4(fa0, a0A); ldsm4(fa1, a1A); ldsm4(fb, bA);
          MMA_BF16(acc[0][0], fa0[0],fa0[1],fa0[2],fa0[3], fb[0], fb[1]);
          MMA_BF16(acc[0][1], fa0[0],fa0[1],fa0[2],fa0[3], fb[2], fb[3]);
          MMA_BF16(acc[1][0], fa1[0],fa1[1],fa1[2],fa1[3], fb[0], fb[1]);
          MMA_BF16(acc[1][1], fa1[0],fa1[1],fa1[2],fa1[3], fb[2], fb[3]);
          a0A += 32; a1A += 32; bA += 32;
        }
      }
      BAR_ARR(9 + wk, 128);                       // hs(t) consumed

      // stage partials: hgb[b][col][wk], row stride 196
      #pragma unroll
      for (int mf = 0; mf < 2; mf++) {
        #pragma unroll
        for (int nf = 0; nf < 2; nf++) {
          int r = mf*16 + tg;
          int col = wn*16 + nf*8 + 2*tc;
          hgb[r*196 + col*4 + wk]         = acc[mf][nf][0];
          hgb[r*196 + (col+1)*4 + wk]     = acc[mf][nf][1];
          hgb[(r+8)*196 + col*4 + wk]     = acc[mf][nf][2];
          hgb[(r+8)*196 + (col+1)*4 + wk] = acc[mf][nf][3];
        }
      }
      if (warp < 8) {
        BAR_SYNC(13, 384);
        __nv_bfloat16* hout = g_hbf[buf ^ 1] + (size_t)stack*B_*D_;
        float hb0f, hb1f;
        #pragma unroll
        for (int half = 0; half < 2; half++) {
          int b = gb + half*16, j = gj;
          float4 pr = *(const float4*)&hgb[b*196 + j*4];
          float4 pz = *(const float4*)&hgb[b*196 + (16 + j)*4];
          float4 pn = *(const float4*)&hgb[b*196 + (32 + j)*4];
          float xr = xgb[b*48 + j];
          float xz = xgb[b*48 + 16 + j];
          float xn = xgb[b*48 + 32 + j];
          float hr = bhh_s[j]      + (pr.x + pr.y + pr.z + pr.w);
          float hz = bhh_s[16 + j] + (pz.x + pz.y + pz.z + pz.w);
          float hn = bhh_s[32 + j] + (pn.x + pn.y + pn.z + pn.w);
          float r  = 1.f/(1.f + __expf(-(xr+hr)));
          float z  = 1.f/(1.f + __expf(-(xz+hz)));
          float nn = fast_tanh(xn + r*hn);
          float hprev = half ? hp1 : hp0;
          float hnew = (1.f - z)*nn + z*hprev;
          if (half) { hp1 = hnew; hb1f = hnew; } else { hp0 = hnew; hb0f = hnew; }
          hout[(size_t)b*D_ + cgb + j] = __float2bfloat16(hnew);
        }
        BAR_SYNC(14, 256);
        if (tid == 0) st_rel(myflag, (unsigned)(t + 1));
        ys[((size_t)t*B_ + gb)*D_ + cgb + gj]      = __float2bfloat16(hb0f);
        ys[((size_t)t*B_ + gb + 16)*D_ + cgb + gj] = __float2bfloat16(hb1f);
      } else {
        BAR_ARR(13, 384);
      }
    }
  }
}

__global__ __launch_bounds__(128) void k_out1(const float* __restrict__ Wo, const float* __restrict__ bo) {
  int row = blockIdx.x;
  int tid = threadIdx.x;
  float acc = 0.f;
  for (int d = tid; d < D_; d += 128)
    acc += (__bfloat162float(g_yf_bf[(size_t)row*D_+d]) +
            __bfloat162float(g_yb_bf[(size_t)row*D_+d])) * Wo[d];
  #pragma unroll
  for (int o = 16; o; o >>= 1) acc += __shfl_xor_sync(0xffffffffu, acc, o);
  __shared__ float ws[4];
  if ((tid & 31) == 0) ws[tid>>5] = acc;
  __syncthreads();
  if (tid == 0) {
    float s = ws[0]+ws[1]+ws[2]+ws[3] + bo[0];
    g_outvals[row] = 1.f/(1.f + expf(-s));
  }
}

__global__ void k_out2(float* out) {
  __shared__ float sm[256];
  int tid = threadIdx.x;
  float s = 0.f;
  for (int i = tid; i < TB_; i += 256) s += g_outvals[i];
  sm[tid] = s;
  __syncthreads();
  for (int o = 128; o; o >>= 1) { if (tid < o) sm[tid] += sm[tid+o]; __syncthreads(); }
  if (tid == 0) out[0] = sm[0] / (float)TB_;
}

extern "C" void kernel_launch(void* const* d_in, const int* in_sizes, int n_in,
                              void* d_out, int out_size) {
  (void)in_sizes; (void)n_in; (void)out_size;
  const float* input = (const float*)d_in[0];
  const float* cond  = (const float*)d_in[1];
  const float* Wc    = (const float*)d_in[2];
  const float* bc    = (const float*)d_in[3];
  const float* Wi    = (const float*)d_in[4];
  const float* bi    = (const float*)d_in[5];
  const float* Wih_f = (const float*)d_in[6];
  const float* Whh_f = (const float*)d_in[7];
  const float* bih_f = (const float*)d_in[8];
  const float* bhh_f = (const float*)d_in[9];
  const float* Wih_b = (const float*)d_in[10];
  const float* Whh_b = (const float*)d_in[11];
  const float* bih_b = (const float*)d_in[12];
  const float* bhh_b = (const float*)d_in[13];
  const float* Wo    = (const float*)d_in[14];
  const float* bo    = (const float*)d_in[15];
  float* out = (float*)d_out;

  cudaFuncSetAttribute(k_rnn, cudaFuncAttributeMaxDynamicSharedMemorySize, RNN_SMEM);

  k_convw<<<4096, 256>>>(Wih_f, Wih_b);
  k_proj<<<256, 256>>>(input, cond, Wc, bc, Wi, bi);
  for (int l = 0; l < L_; l++) {
    k_gemm<<<dim3(48, 64, 2), 256>>>(l, bih_f, bih_b);
    k_rnn<<<NCTA_, 512, RNN_SMEM>>>(l, Whh_f, Whh_b, bhh_f, bhh_b);
  }
  k_out1<<<TB_, 128>>>(Wo, bo);
  k_out2<<<1, 256>>>(out);
}